// round 6
// baseline (speedup 1.0000x reference)
#include <cuda_runtime.h>
#include <math.h>
#include <stdint.h>

// Problem constants
#define BSZ 4
#define NSEQ 2048
#define DMODEL 256
#define HH 8
#define DHD 32
#define RR 64
#define KSP 32
#define MROWS (BSZ * NSEQ)   // 8192
#define TQ 8                 // query rows per fused-attention block

// ---------------------------------------------------------------------------
// Scratch arena (float offsets), compile-time indexed. No scores scratch.
// ---------------------------------------------------------------------------
#define OFF_T   ((size_t)0)                                   // 3 * 8192*64
#define OFF_H   (OFF_T  + (size_t)3 * MROWS * RR)
#define OFF_Q   (OFF_H  + (size_t)MROWS * DMODEL)
#define OFF_K   (OFF_Q  + (size_t)MROWS * DMODEL)
#define OFF_V   (OFF_K  + (size_t)MROWS * DMODEL)
#define OFF_O   (OFF_V  + (size_t)MROWS * DMODEL)
#define OFF_O2  (OFF_O  + (size_t)MROWS * DMODEL)
#define OFF_PS  (OFF_O2 + (size_t)MROWS * DMODEL)
#define OFF_PQ  (OFF_PS + (size_t)64 * DMODEL)
#define OFF_ST  (OFF_PQ + (size_t)64 * DMODEL)
#define ARENA_TOTAL (OFF_ST + (size_t)2 * DMODEL)

__device__ float g_arena[ARENA_TOTAL];

// Dynamic SMEM layout for the fused attention kernel (floats):
//   sc : [0, TQ*NSEQ)            scores tile  (8*2048 = 16384)
//   Ks : [TQ*NSEQ, +128*33)      K tile, pad-33 (4224)
#define SM_SC   0
#define SM_KS   (TQ * NSEQ)
#define SM_DYN_FLOATS (SM_KS + 128 * 33)
#define SM_DYN_BYTES  (SM_DYN_FLOATS * 4)

// ---------------------------------------------------------------------------
// Shared GEMM body: C[M,N] = A[M,K] @ B[K,N] (+ bias[N])
// ---------------------------------------------------------------------------
__device__ __forceinline__ void gemm_body(const float* __restrict__ A,
                                          const float* __restrict__ Bm,
                                          const float* __restrict__ bias,
                                          float* __restrict__ C,
                                          int Nn, int K) {
    __shared__ float As[16][65];
    __shared__ float Bs[16][65];
    int tid = threadIdx.x;
    int tx = tid & 15, ty = tid >> 4;
    int m0 = blockIdx.y * 64, n0 = blockIdx.x * 64;
    float acc[4][4] = {};

    for (int k0 = 0; k0 < K; k0 += 16) {
#pragma unroll
        for (int r = 0; r < 4; r++) {
            int idx = tid + r * 256;
            int m = idx >> 4;
            int kk = idx & 15;
            As[kk][m] = A[(size_t)(m0 + m) * K + k0 + kk];
        }
#pragma unroll
        for (int r = 0; r < 4; r++) {
            int idx = tid + r * 256;
            int kk = idx >> 6;
            int nn = idx & 63;
            Bs[kk][nn] = Bm[(size_t)(k0 + kk) * Nn + n0 + nn];
        }
        __syncthreads();
#pragma unroll
        for (int kk = 0; kk < 16; kk++) {
            float a4[4], b4[4];
#pragma unroll
            for (int i = 0; i < 4; i++) a4[i] = As[kk][ty * 4 + i];
#pragma unroll
            for (int j = 0; j < 4; j++) b4[j] = Bs[kk][tx * 4 + j];
#pragma unroll
            for (int i = 0; i < 4; i++)
#pragma unroll
                for (int j = 0; j < 4; j++)
                    acc[i][j] += a4[i] * b4[j];
        }
        __syncthreads();
    }
#pragma unroll
    for (int i = 0; i < 4; i++) {
        int m = m0 + ty * 4 + i;
#pragma unroll
        for (int j = 0; j < 4; j++) {
            int n = n0 + tx * 4 + j;
            float v = acc[i][j];
            if (bias) v += bias[n];
            C[(size_t)m * Nn + n] = v;
        }
    }
}

__global__ void sgemm_kernel(const float* __restrict__ Aext, size_t aOff,
                             const float* __restrict__ Bm,
                             const float* __restrict__ bias,
                             size_t cOff, int Nn, int K) {
    const float* A = Aext ? Aext : (g_arena + aOff);
    gemm_body(A, Bm, bias, g_arena + cOff, Nn, K);
}

__global__ void sgemm3_kernel(size_t aOff, size_t aStride,
                              const float* __restrict__ B0,
                              const float* __restrict__ B1,
                              const float* __restrict__ B2,
                              size_t cOff, size_t cStride, int Nn, int K) {
    int z = blockIdx.z;
    const float* Bm = (z == 0) ? B0 : (z == 1) ? B1 : B2;
    gemm_body(g_arena + aOff + (size_t)z * aStride, Bm, nullptr,
              g_arena + cOff + (size_t)z * cStride, Nn, K);
}

// ---------------------------------------------------------------------------
// Fused attention: QK^T (scores in SMEM) + exact top-32 radix select +
// sparse softmax + sparse P @ V. One block per (b,h, 8-query tile).
// ---------------------------------------------------------------------------
__device__ __forceinline__ unsigned fkey(float f) {
    unsigned u = __float_as_uint(f);
    return u ^ (((int)u < 0) ? 0xFFFFFFFFu : 0x80000000u);
}

__device__ __forceinline__ float blkReduceMax(float v, float* red) {
#pragma unroll
    for (int o = 16; o; o >>= 1) v = fmaxf(v, __shfl_xor_sync(0xffffffffu, v, o));
    if ((threadIdx.x & 31) == 0) red[threadIdx.x >> 5] = v;
    __syncthreads();
    float m = red[0];
#pragma unroll
    for (int i = 1; i < 8; i++) m = fmaxf(m, red[i]);
    return m;
}

__device__ __forceinline__ float blkReduceSum(float v, float* red) {
#pragma unroll
    for (int o = 16; o; o >>= 1) v += __shfl_xor_sync(0xffffffffu, v, o);
    if ((threadIdx.x & 31) == 0) red[threadIdx.x >> 5] = v;
    __syncthreads();
    float m = red[0];
#pragma unroll
    for (int i = 1; i < 8; i++) m += red[i];
    return m;
}

__global__ void __launch_bounds__(256, 2) attn_fused_kernel() {
    extern __shared__ float dyn[];
    float* sc = dyn + SM_SC;    // [TQ][NSEQ]
    float* Ks = dyn + SM_KS;    // [128][33]

    __shared__ unsigned hist[256];
    __shared__ unsigned wsum[8];
    __shared__ float red[8];
    __shared__ float part[256];
    __shared__ int sel_idx[64];
    __shared__ float sel_p[64];
    __shared__ unsigned sh_pref, sh_k;

    const float* qg = g_arena + OFF_Q;
    const float* kg = g_arena + OFF_K;
    const float* vg = g_arena + OFF_V;
    float* og = g_arena + OFF_O;

    int bh = blockIdx.y;
    int h = bh & (HH - 1), b = bh >> 3;
    int n0 = blockIdx.x * TQ;
    int t = threadIdx.x;
    int lane = t & 31, w = t >> 5;

    // ---- Phase 1: scores sc[q][j] = (q_row . k_j) / sqrt(32) ----
    // Thread group tg = t>>6 owns queries {2tg, 2tg+1} with Q in registers;
    // kl = t&63 covers keys {kl, kl+64} of each 128-key tile.
    int tg = t >> 6, kl = t & 63;
    int q0 = tg * 2, q1 = q0 + 1;
    const float* qrow0 = qg + ((size_t)(b * NSEQ + n0 + q0)) * DMODEL + h * DHD;
    const float* qrow1 = qg + ((size_t)(b * NSEQ + n0 + q1)) * DMODEL + h * DHD;
    float Qa[DHD], Qb[DHD];
#pragma unroll
    for (int d = 0; d < DHD; d++) {
        Qa[d] = qrow0[d];       // same line across 64 threads -> L1 broadcast
        Qb[d] = qrow1[d];
    }
    const float* kbase = kg + ((size_t)b * NSEQ) * DMODEL + h * DHD;
    const float scale = 1.0f / sqrtf((float)DHD);

    for (int kt = 0; kt < NSEQ / 128; kt++) {
        // load K tile (128 rows x 32) coalesced, pad-33 in SMEM
        for (int e = t; e < 128 * DHD; e += 256) {
            int kr = e >> 5, kd = e & 31;
            Ks[kr * 33 + kd] = kbase[(size_t)(kt * 128 + kr) * DMODEL + kd];
        }
        __syncthreads();
        float a00 = 0.f, a01 = 0.f, a10 = 0.f, a11 = 0.f;
        const float* k0p = Ks + kl * 33;
        const float* k1p = Ks + (kl + 64) * 33;
#pragma unroll
        for (int d = 0; d < DHD; d++) {
            float kv0 = k0p[d], kv1 = k1p[d];
            a00 += Qa[d] * kv0;
            a01 += Qa[d] * kv1;
            a10 += Qb[d] * kv0;
            a11 += Qb[d] * kv1;
        }
        int jb = kt * 128;
        sc[q0 * NSEQ + jb + kl]      = a00 * scale;
        sc[q0 * NSEQ + jb + kl + 64] = a01 * scale;
        sc[q1 * NSEQ + jb + kl]      = a10 * scale;
        sc[q1 * NSEQ + jb + kl + 64] = a11 * scale;
        __syncthreads();
    }

    // ---- Phase 2: per row: top-32 radix select + sparse softmax + PV ----
    const float* vbp = vg + ((size_t)b * NSEQ) * DMODEL + h * DHD + lane;

    for (int r = 0; r < TQ; r++) {
        const float* srow = sc + r * NSEQ;

        // thread t owns elements j = t + 256*i (conflict-free SMEM reads)
        float val8[8];
        unsigned key8[8];
        float m = -INFINITY;
#pragma unroll
        for (int i = 0; i < 8; i++) {
            float sv = srow[t + 256 * i];
            val8[i] = sv;
            key8[i] = fkey(sv);
            m = fmaxf(m, sv);
        }
        if (t == 0) { sh_pref = 0u; sh_k = KSP; }
        m = blkReduceMax(m, red);   // its sync publishes sh_pref/sh_k

        // Radix select: exact 32nd-largest key (ties counted — matches
        // jax.lax.top_k's k-th sorted value under >= threshold semantics).
#pragma unroll 1
        for (int shift = 24; shift >= 0; shift -= 8) {
            hist[t] = 0u;
            unsigned pref = sh_pref;
            unsigned kneed = sh_k;
            __syncthreads();
            unsigned mask = (shift == 24) ? 0u : (0xFFFFFFFFu << (shift + 8));
#pragma unroll
            for (int i = 0; i < 8; i++)
                if ((key8[i] & mask) == pref)
                    atomicAdd(&hist[(key8[i] >> shift) & 255u], 1u);
            __syncthreads();
            unsigned own = hist[t];
            unsigned sv = own;
#pragma unroll
            for (int off = 1; off < 32; off <<= 1) {
                unsigned u = __shfl_down_sync(0xffffffffu, sv, off);
                if (lane + off < 32) sv += u;
            }
            if (lane == 0) wsum[w] = sv;
            __syncthreads();
            unsigned add = 0u;
#pragma unroll
            for (int w2 = 0; w2 < 8; w2++)
                if (w2 > w) add += wsum[w2];
            unsigned suf = sv + add;
            if (suf >= kneed && (suf - own) < kneed) {
                sh_pref = pref | ((unsigned)t << shift);
                sh_k = kneed - (suf - own);
            }
            __syncthreads();
        }
        unsigned thr = sh_pref;

        // Deterministic compaction (rank by (t, i) order), capped at 64.
        unsigned pass8 = 0u;
        unsigned cnt_t = 0u;
#pragma unroll
        for (int i = 0; i < 8; i++)
            if (key8[i] >= thr) { pass8 |= (1u << i); cnt_t++; }
        unsigned pv = cnt_t;
#pragma unroll
        for (int off = 1; off < 32; off <<= 1) {
            unsigned u = __shfl_up_sync(0xffffffffu, pv, off);
            if (lane >= off) pv += u;
        }
        if (lane == 31) wsum[w] = pv;
        __syncthreads();
        unsigned addp = 0u, cnt_all = 0u;
#pragma unroll
        for (int w2 = 0; w2 < 8; w2++) {
            unsigned ws = wsum[w2];
            if (w2 < w) addp += ws;
            cnt_all += ws;
        }
        int pos = (int)(pv + addp - cnt_t);
        int cnt = (int)cnt_all;
#pragma unroll
        for (int i = 0; i < 8; i++)
            if (pass8 & (1u << i)) {
                if (pos < 64) { sel_idx[pos] = t + 256 * i; sel_p[pos] = val8[i]; }
                pos++;
            }
        __syncthreads();

        float acc = 0.f;
        float inv;
        if (cnt <= 64) {
            // Sparse path (essentially always): exp + sum over cnt entries.
            float loc = 0.f;
            for (int e = t; e < cnt; e += 256) {
                float p = __expf(sel_p[e] - m);
                sel_p[e] = p;
                loc += p;
            }
            float tot = blkReduceSum(loc, red);   // sync publishes sel_p
            inv = 1.f / tot;
            // Sparse P @ V: warp w handles entries e ≡ w (mod 8); lane
            // gathers V[sel_idx[e]][h*32+lane] — coalesced 128B rows.
            for (int e = w; e < cnt; e += 8)
                acc += sel_p[e] * vbp[(size_t)sel_idx[e] * DMODEL];
        } else {
            // Tie-overflow fallback (block-uniform branch, deterministic).
            float loc = 0.f;
#pragma unroll
            for (int i = 0; i < 8; i++)
                loc += (key8[i] >= thr) ? __expf(val8[i] - m) : 0.f;
            float tot = blkReduceSum(loc, red);
            inv = 1.f / tot;
            for (int j = w; j < NSEQ; j += 8) {
                float sv = srow[j];
                if (fkey(sv) >= thr)
                    acc += __expf(sv - m) * vbp[(size_t)j * DMODEL];
            }
        }
        part[t] = acc;
        __syncthreads();
        if (t < 32) {
            float rsum = part[t];
#pragma unroll
            for (int ww = 1; ww < 8; ww++) rsum += part[ww * 32 + t];
            og[((size_t)(b * NSEQ + n0 + r)) * DMODEL + h * DHD + t] = rsum * inv;
        }
        __syncthreads();   // part[]/sel reuse barrier before next row
    }
}

// ---------------------------------------------------------------------------
// BatchNorm over (B,N) per channel — deterministic two-stage reduction.
// ---------------------------------------------------------------------------
__global__ void bn_partial_kernel() {
    const float* X = g_arena + OFF_H;
    float* ps = g_arena + OFF_PS;
    float* pq = g_arena + OFF_PQ;
    int blk = blockIdx.x;
    int t = threadIdx.x;
    float s = 0.f, q = 0.f;
    for (int r = 0; r < 128; r++) {
        float val = X[(size_t)(blk * 128 + r) * DMODEL + t];
        s += val;
        q += val * val;
    }
    ps[blk * DMODEL + t] = s;
    pq[blk * DMODEL + t] = q;
}

__global__ void bn_finalize_kernel() {
    const float* ps = g_arena + OFF_PS;
    const float* pq = g_arena + OFF_PQ;
    float* stat = g_arena + OFF_ST;
    int t = threadIdx.x;
    float s = 0.f, q = 0.f;
    for (int b = 0; b < 64; b++) {
        s += ps[b * DMODEL + t];
        q += pq[b * DMODEL + t];
    }
    float mu = s * (1.0f / (float)MROWS);
    float var = q * (1.0f / (float)MROWS) - mu * mu;
    stat[t] = mu;
    stat[DMODEL + t] = rsqrtf(var + 1e-5f);
}

__global__ void bn_apply_kernel(const float* __restrict__ gamma,
                                const float* __restrict__ beta,
                                float* __restrict__ out) {
    const float* X = g_arena + OFF_H;
    const float* stat = g_arena + OFF_ST;
    size_t idx = (size_t)blockIdx.x * 256 + threadIdx.x;
    int c = (int)(idx & (DMODEL - 1));
    out[idx] = (X[idx] - stat[c]) * stat[DMODEL + c] * gamma[c] + beta[c];
}

// ---------------------------------------------------------------------------
// Launch — kernel launches + one idempotent attribute set (not a stream op)
// ---------------------------------------------------------------------------
extern "C" void kernel_launch(void* const* d_in, const int* in_sizes, int n_in,
                              void* d_out, int out_size) {
    const float* x    = (const float*)d_in[0];
    const float* U_np = (const float*)d_in[1];
    const float* V_np = (const float*)d_in[2];
    const float* b_np = (const float*)d_in[3];
    const float* U_q  = (const float*)d_in[4];
    const float* V_q  = (const float*)d_in[5];
    const float* U_k  = (const float*)d_in[6];
    const float* V_k  = (const float*)d_in[7];
    const float* U_v  = (const float*)d_in[8];
    const float* V_v  = (const float*)d_in[9];
    const float* U_o  = (const float*)d_in[10];
    const float* V_o  = (const float*)d_in[11];
    const float* b_o  = (const float*)d_in[12];
    const float* U_op = (const float*)d_in[13];
    const float* V_op = (const float*)d_in[14];
    const float* b_op = (const float*)d_in[15];
    const float* gamma = (const float*)d_in[16];
    const float* beta  = (const float*)d_in[17];
    float* out = (float*)d_out;

    cudaFuncSetAttribute(attn_fused_kernel,
                         cudaFuncAttributeMaxDynamicSharedMemorySize,
                         SM_DYN_BYTES);

    dim3 gN1(1, MROWS / 64);        // Nn = 64
    dim3 gN4(4, MROWS / 64);        // Nn = 256
    dim3 gN1z(1, MROWS / 64, 3);    // batched QKV stage-1
    dim3 gN4z(4, MROWS / 64, 3);    // batched QKV stage-2

    // h = (x @ U_np) @ V_np + b_np
    sgemm_kernel<<<gN1, 256>>>(x, 0, U_np, nullptr, OFF_T, RR, DMODEL);
    sgemm_kernel<<<gN4, 256>>>(nullptr, OFF_T, V_np, b_np, OFF_H, DMODEL, RR);
    // q,k,v batched
    sgemm3_kernel<<<gN1z, 256>>>(OFF_H, 0, U_q, U_k, U_v,
                                 OFF_T, (size_t)MROWS * RR, RR, DMODEL);
    sgemm3_kernel<<<gN4z, 256>>>(OFF_T, (size_t)MROWS * RR, V_q, V_k, V_v,
                                 OFF_Q, (size_t)MROWS * DMODEL, DMODEL, RR);

    // fused QK + top-k + softmax + sparse PV
    attn_fused_kernel<<<dim3(NSEQ / TQ, BSZ * HH), 256, SM_DYN_BYTES>>>();

    // attention out proj + out_proj
    sgemm_kernel<<<gN1, 256>>>(nullptr, OFF_O, U_o, nullptr, OFF_T, RR, DMODEL);
    sgemm_kernel<<<gN4, 256>>>(nullptr, OFF_T, V_o, b_o, OFF_O2, DMODEL, RR);
    sgemm_kernel<<<gN1, 256>>>(nullptr, OFF_O2, U_op, nullptr, OFF_T, RR, DMODEL);
    sgemm_kernel<<<gN4, 256>>>(nullptr, OFF_T, V_op, b_op, OFF_H, DMODEL, RR);

    // BatchNorm
    bn_partial_kernel<<<64, 256>>>();
    bn_finalize_kernel<<<1, 256>>>();
    bn_apply_kernel<<<(MROWS * DMODEL) / 256, 256>>>(gamma, beta, out);
}

// round 9
// speedup vs baseline: 1.5942x; 1.5942x over previous
#include <cuda_runtime.h>
#include <math.h>
#include <stdint.h>

// Problem constants
#define BSZ 4
#define NSEQ 2048
#define DMODEL 256
#define HH 8
#define DHD 32
#define RR 64
#define KSP 32
#define MROWS (BSZ * NSEQ)   // 8192

// ---------------------------------------------------------------------------
// Scratch arena (float offsets), compile-time indexed.
// ---------------------------------------------------------------------------
#define OFF_T   ((size_t)0)                                   // 3 * 8192*64
#define OFF_H   (OFF_T  + (size_t)3 * MROWS * RR)
#define OFF_Q   (OFF_H  + (size_t)MROWS * DMODEL)
#define OFF_K   (OFF_Q  + (size_t)MROWS * DMODEL)
#define OFF_V   (OFF_K  + (size_t)MROWS * DMODEL)
#define OFF_O   (OFF_V  + (size_t)MROWS * DMODEL)
#define OFF_O2  (OFF_O  + (size_t)MROWS * DMODEL)
#define OFF_SC  (OFF_O2 + (size_t)MROWS * DMODEL)             // 512 MB scores
#define OFF_PS  (OFF_SC + (size_t)BSZ * HH * NSEQ * NSEQ)
#define OFF_PQ  (OFF_PS + (size_t)64 * DMODEL)
#define OFF_ST  (OFF_PQ + (size_t)64 * DMODEL)
#define ARENA_TOTAL (OFF_ST + (size_t)2 * DMODEL)

__device__ float g_arena[ARENA_TOTAL];

// ---------------------------------------------------------------------------
// Shared GEMM body: C[M,N] = A[M,K] @ B[K,N] (+ bias[N])
// ---------------------------------------------------------------------------
__device__ __forceinline__ void gemm_body(const float* __restrict__ A,
                                          const float* __restrict__ Bm,
                                          const float* __restrict__ bias,
                                          float* __restrict__ C,
                                          int Nn, int K) {
    __shared__ float As[16][65];
    __shared__ float Bs[16][65];
    int tid = threadIdx.x;
    int tx = tid & 15, ty = tid >> 4;
    int m0 = blockIdx.y * 64, n0 = blockIdx.x * 64;
    float acc[4][4] = {};

    for (int k0 = 0; k0 < K; k0 += 16) {
#pragma unroll
        for (int r = 0; r < 4; r++) {
            int idx = tid + r * 256;
            int m = idx >> 4;
            int kk = idx & 15;
            As[kk][m] = A[(size_t)(m0 + m) * K + k0 + kk];
        }
#pragma unroll
        for (int r = 0; r < 4; r++) {
            int idx = tid + r * 256;
            int kk = idx >> 6;
            int nn = idx & 63;
            Bs[kk][nn] = Bm[(size_t)(k0 + kk) * Nn + n0 + nn];
        }
        __syncthreads();
#pragma unroll
        for (int kk = 0; kk < 16; kk++) {
            float a4[4], b4[4];
#pragma unroll
            for (int i = 0; i < 4; i++) a4[i] = As[kk][ty * 4 + i];
#pragma unroll
            for (int j = 0; j < 4; j++) b4[j] = Bs[kk][tx * 4 + j];
#pragma unroll
            for (int i = 0; i < 4; i++)
#pragma unroll
                for (int j = 0; j < 4; j++)
                    acc[i][j] += a4[i] * b4[j];
        }
        __syncthreads();
    }
#pragma unroll
    for (int i = 0; i < 4; i++) {
        int m = m0 + ty * 4 + i;
#pragma unroll
        for (int j = 0; j < 4; j++) {
            int n = n0 + tx * 4 + j;
            float v = acc[i][j];
            if (bias) v += bias[n];
            C[(size_t)m * Nn + n] = v;
        }
    }
}

__global__ void sgemm_kernel(const float* __restrict__ Aext, size_t aOff,
                             const float* __restrict__ Bm,
                             const float* __restrict__ bias,
                             size_t cOff, int Nn, int K) {
    const float* A = Aext ? Aext : (g_arena + aOff);
    gemm_body(A, Bm, bias, g_arena + cOff, Nn, K);
}

__global__ void sgemm3_kernel(size_t aOff, size_t aStride,
                              const float* __restrict__ B0,
                              const float* __restrict__ B1,
                              const float* __restrict__ B2,
                              size_t cOff, size_t cStride, int Nn, int K) {
    int z = blockIdx.z;
    const float* Bm = (z == 0) ? B0 : (z == 1) ? B1 : B2;
    gemm_body(g_arena + aOff + (size_t)z * aStride, Bm, nullptr,
              g_arena + cOff + (size_t)z * cStride, Nn, K);
}

// ---------------------------------------------------------------------------
// QK^T scores per (b,h): S[bh][i][j] = (q_i . k_j) / sqrt(32)
// Plain float4 stores (NOT __stcs — keep the stream's L2 tail warm for the
// consumer kernel's read-back).
// ---------------------------------------------------------------------------
__global__ void qk_kernel() {
    const float* q = g_arena + OFF_Q;
    const float* k = g_arena + OFF_K;
    float* S = g_arena + OFF_SC;
    int bh = blockIdx.z;
    int h = bh & (HH - 1), b = bh >> 3;
    int i0 = blockIdx.y * 64, j0 = blockIdx.x * 64;
    __shared__ float Qs[64][33];
    __shared__ float Ks[64][33];
    int tid = threadIdx.x;
    int d = tid & 31, r0 = tid >> 5;
    const float* qb = q + ((size_t)b * NSEQ) * DMODEL + h * DHD;
    const float* kb = k + ((size_t)b * NSEQ) * DMODEL + h * DHD;
#pragma unroll
    for (int r = r0; r < 64; r += 8) {
        Qs[r][d] = qb[(size_t)(i0 + r) * DMODEL + d];
        Ks[r][d] = kb[(size_t)(j0 + r) * DMODEL + d];
    }
    __syncthreads();
    int tx = tid & 15, ty = tid >> 4;
    float acc[4][4] = {};
#pragma unroll
    for (int dd = 0; dd < 32; dd++) {
        float a4[4], b4[4];
#pragma unroll
        for (int i = 0; i < 4; i++) a4[i] = Qs[ty * 4 + i][dd];
#pragma unroll
        for (int j = 0; j < 4; j++) b4[j] = Ks[tx * 4 + j][dd];
#pragma unroll
        for (int i = 0; i < 4; i++)
#pragma unroll
            for (int j = 0; j < 4; j++)
                acc[i][j] += a4[i] * b4[j];
    }
    const float scale = 1.0f / sqrtf(32.0f);
    float* Sp = S + ((size_t)bh * NSEQ + i0) * NSEQ + j0;
#pragma unroll
    for (int i = 0; i < 4; i++) {
        float4 v4 = make_float4(acc[i][0] * scale, acc[i][1] * scale,
                                acc[i][2] * scale, acc[i][3] * scale);
        *reinterpret_cast<float4*>(Sp + (size_t)(ty * 4 + i) * NSEQ + tx * 4) = v4;
    }
}

// ---------------------------------------------------------------------------
// Fused per-row: exact top-32 via radix select (match_any leader-atomic
// histograms + early exit), deterministic compaction, sparse exp + P @ V.
// ---------------------------------------------------------------------------
__device__ __forceinline__ unsigned fkey(float f) {
    unsigned u = __float_as_uint(f);
    return u ^ (((int)u < 0) ? 0xFFFFFFFFu : 0x80000000u);
}

__device__ __forceinline__ float blkReduceMax(float v, float* red) {
#pragma unroll
    for (int o = 16; o; o >>= 1) v = fmaxf(v, __shfl_xor_sync(0xffffffffu, v, o));
    if ((threadIdx.x & 31) == 0) red[threadIdx.x >> 5] = v;
    __syncthreads();
    float m = red[0];
#pragma unroll
    for (int i = 1; i < 8; i++) m = fmaxf(m, red[i]);
    return m;
}

__device__ __forceinline__ float blkReduceSum(float v, float* red) {
#pragma unroll
    for (int o = 16; o; o >>= 1) v += __shfl_xor_sync(0xffffffffu, v, o);
    if ((threadIdx.x & 31) == 0) red[threadIdx.x >> 5] = v;
    __syncthreads();
    float m = red[0];
#pragma unroll
    for (int i = 1; i < 8; i++) m += red[i];
    return m;
}

__global__ void attn_row_kernel() {
    const float* S = g_arena + OFF_SC;
    const float* v = g_arena + OFF_V;
    float* o = g_arena + OFF_O;

    __shared__ unsigned hist[256];
    __shared__ unsigned wsum[8];
    __shared__ int sel_idx[NSEQ];
    __shared__ float sel_p[NSEQ];
    __shared__ float red[8];
    __shared__ float part[256];
    __shared__ unsigned sh_pref, sh_k, sh_done;

    int row = blockIdx.x;
    int n = row & (NSEQ - 1);
    int bh = row >> 11;
    int h = bh & (HH - 1), b = bh >> 3;
    int t = threadIdx.x;
    int lane = t & 31, w = t >> 5;

    const float4* srow4 = reinterpret_cast<const float4*>(
        S + ((size_t)bh * NSEQ + n) * NSEQ);

    // Thread t owns indices 8t..8t+7 (two streaming float4 loads).
    float val8[8];
    unsigned key8[8];
    float4 va = __ldcs(srow4 + 2 * t);
    float4 vb = __ldcs(srow4 + 2 * t + 1);
    val8[0] = va.x; val8[1] = va.y; val8[2] = va.z; val8[3] = va.w;
    val8[4] = vb.x; val8[5] = vb.y; val8[6] = vb.z; val8[7] = vb.w;
    float m = -INFINITY;
#pragma unroll
    for (int r = 0; r < 8; r++) {
        key8[r] = fkey(val8[r]);
        m = fmaxf(m, val8[r]);
    }
    if (t == 0) { sh_pref = 0u; sh_k = KSP; sh_done = 0u; }
    m = blkReduceMax(m, red);   // its sync publishes sh_pref/sh_k/sh_done

    // Radix select for the exact 32nd-largest key (ties counted — matches
    // jax.lax.top_k's k-th sorted value under >= threshold semantics).
    // Histogram via match_any: one leader atomic per distinct bucket per
    // warp-round — removes the same-bucket smem-atomic serialization.
    // Early exit: if the selected bucket is entirely kept (suf == kneed),
    // thr = prefix (zero low bits) is already exact.
#pragma unroll 1
    for (int shift = 24; shift >= 0; shift -= 8) {
        if (sh_done) break;
        hist[t] = 0u;
        unsigned pref = sh_pref;
        unsigned kneed = sh_k;
        __syncthreads();
        unsigned mask = (shift == 24) ? 0u : (0xFFFFFFFFu << (shift + 8));
#pragma unroll
        for (int r = 0; r < 8; r++) {
            bool act = (key8[r] & mask) == pref;
            unsigned bucket = act ? ((key8[r] >> shift) & 255u) : 256u;
            unsigned grp = __match_any_sync(0xffffffffu, bucket);
            if (act && lane == (__ffs(grp) - 1))
                atomicAdd(&hist[bucket], __popc(grp));
        }
        __syncthreads();
        unsigned own = hist[t];
        // warp-level inclusive suffix scan of the 256 buckets
        unsigned sv = own;
#pragma unroll
        for (int off = 1; off < 32; off <<= 1) {
            unsigned u = __shfl_down_sync(0xffffffffu, sv, off);
            if (lane + off < 32) sv += u;
        }
        if (lane == 0) wsum[w] = sv;
        __syncthreads();
        unsigned add = 0u;
#pragma unroll
        for (int w2 = 0; w2 < 8; w2++)
            if (w2 > w) add += wsum[w2];
        unsigned suf = sv + add;
        if (suf >= kneed && (suf - own) < kneed) {
            sh_pref = pref | ((unsigned)t << shift);
            sh_k = kneed - (suf - own);
            if (suf == kneed) sh_done = 1u;
        }
        __syncthreads();
    }
    unsigned thr = sh_pref;

    // Deterministic compaction (rank by global index order).
    unsigned pass8 = 0u;
    unsigned cnt_t = 0u;
#pragma unroll
    for (int r = 0; r < 8; r++)
        if (key8[r] >= thr) { pass8 |= (1u << r); cnt_t++; }
    unsigned pv = cnt_t;
#pragma unroll
    for (int off = 1; off < 32; off <<= 1) {
        unsigned u = __shfl_up_sync(0xffffffffu, pv, off);
        if (lane >= off) pv += u;
    }
    if (lane == 31) wsum[w] = pv;
    __syncthreads();
    unsigned addp = 0u, cnt_all = 0u;
#pragma unroll
    for (int w2 = 0; w2 < 8; w2++) {
        unsigned ws = wsum[w2];
        if (w2 < w) addp += ws;
        cnt_all += ws;
    }
    int pos = (int)(pv + addp - cnt_t);
    int cnt = (int)cnt_all;
#pragma unroll
    for (int r = 0; r < 8; r++)
        if (pass8 & (1u << r)) {
            sel_idx[pos] = 8 * t + r;
            sel_p[pos] = val8[r];
            pos++;
        }
    __syncthreads();

    // Sparse exp + sum (~32 entries)
    float loc = 0.f;
    for (int e = t; e < cnt; e += 256) {
        float p = __expf(sel_p[e] - m);
        sel_p[e] = p;
        loc += p;
    }
    float tot = blkReduceSum(loc, red);
    float inv = 1.f / tot;

    // Sparse P @ V: warp w handles entries e ≡ w (mod 8); lane gathers
    // V[sel_idx[e]][h*32+lane] — one coalesced 128B row per entry.
    const float* vbp = v + ((size_t)b * NSEQ) * DMODEL + h * DHD + lane;
    float acc = 0.f;
    for (int e = w; e < cnt; e += 8)
        acc += sel_p[e] * vbp[(size_t)sel_idx[e] * DMODEL];
    part[t] = acc;
    __syncthreads();
    if (t < 32) {
        float r = part[t];
#pragma unroll
        for (int ww = 1; ww < 8; ww++) r += part[ww * 32 + t];
        o[((size_t)b * NSEQ + n) * DMODEL + h * DHD + t] = r * inv;
    }
}

// ---------------------------------------------------------------------------
// BatchNorm over (B,N) per channel — deterministic two-stage reduction.
// ---------------------------------------------------------------------------
__global__ void bn_partial_kernel() {
    const float* X = g_arena + OFF_H;
    float* ps = g_arena + OFF_PS;
    float* pq = g_arena + OFF_PQ;
    int blk = blockIdx.x;
    int t = threadIdx.x;
    float s = 0.f, q = 0.f;
    for (int r = 0; r < 128; r++) {
        float val = X[(size_t)(blk * 128 + r) * DMODEL + t];
        s += val;
        q += val * val;
    }
    ps[blk * DMODEL + t] = s;
    pq[blk * DMODEL + t] = q;
}

__global__ void bn_finalize_kernel() {
    const float* ps = g_arena + OFF_PS;
    const float* pq = g_arena + OFF_PQ;
    float* stat = g_arena + OFF_ST;
    int t = threadIdx.x;
    float s = 0.f, q = 0.f;
    for (int b = 0; b < 64; b++) {
        s += ps[b * DMODEL + t];
        q += pq[b * DMODEL + t];
    }
    float mu = s * (1.0f / (float)MROWS);
    float var = q * (1.0f / (float)MROWS) - mu * mu;
    stat[t] = mu;
    stat[DMODEL + t] = rsqrtf(var + 1e-5f);
}

__global__ void bn_apply_kernel(const float* __restrict__ gamma,
                                const float* __restrict__ beta,
                                float* __restrict__ out) {
    const float* X = g_arena + OFF_H;
    const float* stat = g_arena + OFF_ST;
    size_t idx = (size_t)blockIdx.x * 256 + threadIdx.x;
    int c = (int)(idx & (DMODEL - 1));
    out[idx] = (X[idx] - stat[c]) * stat[DMODEL + c] * gamma[c] + beta[c];
}

// ---------------------------------------------------------------------------
// Launch — kernel launches ONLY (graph-capture safe)
// ---------------------------------------------------------------------------
extern "C" void kernel_launch(void* const* d_in, const int* in_sizes, int n_in,
                              void* d_out, int out_size) {
    const float* x    = (const float*)d_in[0];
    const float* U_np = (const float*)d_in[1];
    const float* V_np = (const float*)d_in[2];
    const float* b_np = (const float*)d_in[3];
    const float* U_q  = (const float*)d_in[4];
    const float* V_q  = (const float*)d_in[5];
    const float* U_k  = (const float*)d_in[6];
    const float* V_k  = (const float*)d_in[7];
    const float* U_v  = (const float*)d_in[8];
    const float* V_v  = (const float*)d_in[9];
    const float* U_o  = (const float*)d_in[10];
    const float* V_o  = (const float*)d_in[11];
    const float* b_o  = (const float*)d_in[12];
    const float* U_op = (const float*)d_in[13];
    const float* V_op = (const float*)d_in[14];
    const float* b_op = (const float*)d_in[15];
    const float* gamma = (const float*)d_in[16];
    const float* beta  = (const float*)d_in[17];
    float* out = (float*)d_out;

    dim3 gN1(1, MROWS / 64);        // Nn = 64
    dim3 gN4(4, MROWS / 64);        // Nn = 256
    dim3 gN1z(1, MROWS / 64, 3);    // batched QKV stage-1
    dim3 gN4z(4, MROWS / 64, 3);    // batched QKV stage-2

    // h = (x @ U_np) @ V_np + b_np
    sgemm_kernel<<<gN1, 256>>>(x, 0, U_np, nullptr, OFF_T, RR, DMODEL);
    sgemm_kernel<<<gN4, 256>>>(nullptr, OFF_T, V_np, b_np, OFF_H, DMODEL, RR);
    // q,k,v batched
    sgemm3_kernel<<<gN1z, 256>>>(OFF_H, 0, U_q, U_k, U_v,
                                 OFF_T, (size_t)MROWS * RR, RR, DMODEL);
    sgemm3_kernel<<<gN4z, 256>>>(OFF_T, (size_t)MROWS * RR, V_q, V_k, V_v,
                                 OFF_Q, (size_t)MROWS * DMODEL, DMODEL, RR);

    // scores
    qk_kernel<<<dim3(NSEQ / 64, NSEQ / 64, BSZ * HH), 256>>>();
    // top-k + softmax + sparse PV
    attn_row_kernel<<<BSZ * HH * NSEQ, 256>>>();

    // attention out proj + out_proj
    sgemm_kernel<<<gN1, 256>>>(nullptr, OFF_O, U_o, nullptr, OFF_T, RR, DMODEL);
    sgemm_kernel<<<gN4, 256>>>(nullptr, OFF_T, V_o, b_o, OFF_O2, DMODEL, RR);
    sgemm_kernel<<<gN1, 256>>>(nullptr, OFF_O2, U_op, nullptr, OFF_T, RR, DMODEL);
    sgemm_kernel<<<gN4, 256>>>(nullptr, OFF_T, V_op, b_op, OFF_H, DMODEL, RR);

    // BatchNorm
    bn_partial_kernel<<<64, 256>>>();
    bn_finalize_kernel<<<1, 256>>>();
    bn_apply_kernel<<<(MROWS * DMODEL) / 256, 256>>>(gamma, beta, out);
}

// round 10
// speedup vs baseline: 1.6997x; 1.0662x over previous
#include <cuda_runtime.h>
#include <math.h>
#include <stdint.h>

// Problem constants
#define BSZ 4
#define NSEQ 2048
#define DMODEL 256
#define HH 8
#define DHD 32
#define RR 64
#define KSP 32
#define MROWS (BSZ * NSEQ)   // 8192

// ---------------------------------------------------------------------------
// Scratch arena (float offsets), compile-time indexed.
// ---------------------------------------------------------------------------
#define OFF_T   ((size_t)0)                                   // 3 * 8192*64
#define OFF_H   (OFF_T  + (size_t)3 * MROWS * RR)
#define OFF_Q   (OFF_H  + (size_t)MROWS * DMODEL)
#define OFF_K   (OFF_Q  + (size_t)MROWS * DMODEL)
#define OFF_V   (OFF_K  + (size_t)MROWS * DMODEL)
#define OFF_O   (OFF_V  + (size_t)MROWS * DMODEL)
#define OFF_O2  (OFF_O  + (size_t)MROWS * DMODEL)
#define OFF_SC  (OFF_O2 + (size_t)MROWS * DMODEL)             // 512 MB scores
#define OFF_PS  (OFF_SC + (size_t)BSZ * HH * NSEQ * NSEQ)
#define OFF_PQ  (OFF_PS + (size_t)64 * DMODEL)
#define OFF_ST  (OFF_PQ + (size_t)64 * DMODEL)
#define ARENA_TOTAL (OFF_ST + (size_t)2 * DMODEL)

__device__ float g_arena[ARENA_TOTAL];

// ---------------------------------------------------------------------------
// Shared GEMM body: C[M,N] = A[M,K] @ B[K,N] (+ bias[N])
// ---------------------------------------------------------------------------
__device__ __forceinline__ void gemm_body(const float* __restrict__ A,
                                          const float* __restrict__ Bm,
                                          const float* __restrict__ bias,
                                          float* __restrict__ C,
                                          int Nn, int K) {
    __shared__ float As[16][65];
    __shared__ float Bs[16][65];
    int tid = threadIdx.x;
    int tx = tid & 15, ty = tid >> 4;
    int m0 = blockIdx.y * 64, n0 = blockIdx.x * 64;
    float acc[4][4] = {};

    for (int k0 = 0; k0 < K; k0 += 16) {
#pragma unroll
        for (int r = 0; r < 4; r++) {
            int idx = tid + r * 256;
            int m = idx >> 4;
            int kk = idx & 15;
            As[kk][m] = A[(size_t)(m0 + m) * K + k0 + kk];
        }
#pragma unroll
        for (int r = 0; r < 4; r++) {
            int idx = tid + r * 256;
            int kk = idx >> 6;
            int nn = idx & 63;
            Bs[kk][nn] = Bm[(size_t)(k0 + kk) * Nn + n0 + nn];
        }
        __syncthreads();
#pragma unroll
        for (int kk = 0; kk < 16; kk++) {
            float a4[4], b4[4];
#pragma unroll
            for (int i = 0; i < 4; i++) a4[i] = As[kk][ty * 4 + i];
#pragma unroll
            for (int j = 0; j < 4; j++) b4[j] = Bs[kk][tx * 4 + j];
#pragma unroll
            for (int i = 0; i < 4; i++)
#pragma unroll
                for (int j = 0; j < 4; j++)
                    acc[i][j] += a4[i] * b4[j];
        }
        __syncthreads();
    }
#pragma unroll
    for (int i = 0; i < 4; i++) {
        int m = m0 + ty * 4 + i;
#pragma unroll
        for (int j = 0; j < 4; j++) {
            int n = n0 + tx * 4 + j;
            float v = acc[i][j];
            if (bias) v += bias[n];
            C[(size_t)m * Nn + n] = v;
        }
    }
}

__global__ void sgemm_kernel(const float* __restrict__ Aext, size_t aOff,
                             const float* __restrict__ Bm,
                             const float* __restrict__ bias,
                             size_t cOff, int Nn, int K) {
    const float* A = Aext ? Aext : (g_arena + aOff);
    gemm_body(A, Bm, bias, g_arena + cOff, Nn, K);
}

__global__ void sgemm3_kernel(size_t aOff, size_t aStride,
                              const float* __restrict__ B0,
                              const float* __restrict__ B1,
                              const float* __restrict__ B2,
                              size_t cOff, size_t cStride, int Nn, int K) {
    int z = blockIdx.z;
    const float* Bm = (z == 0) ? B0 : (z == 1) ? B1 : B2;
    gemm_body(g_arena + aOff + (size_t)z * aStride, Bm, nullptr,
              g_arena + cOff + (size_t)z * cStride, Nn, K);
}

// ---------------------------------------------------------------------------
// QK^T scores per (b,h): S[bh][i][j] = (q_i . k_j) / sqrt(32)
// 128x128 tile, 256 threads, 8x8 per thread. SMEM transposed [d][row] so the
// inner loop uses float4 LDS (4 x LDS.128 per 64 FMA -> FMA-issue-bound).
// ---------------------------------------------------------------------------
__global__ void __launch_bounds__(256, 2) qk_kernel() {
    const float* q = g_arena + OFF_Q;
    const float* k = g_arena + OFF_K;
    float* S = g_arena + OFF_SC;
    int bh = blockIdx.z;
    int h = bh & (HH - 1), b = bh >> 3;
    int i0 = blockIdx.y * 128, j0 = blockIdx.x * 128;

    __shared__ __align__(16) float Qt[DHD][132];   // [d][row]
    __shared__ __align__(16) float Kt[DHD][132];

    int tid = threadIdx.x;
    const float* qb = q + ((size_t)b * NSEQ) * DMODEL + h * DHD;
    const float* kb = k + ((size_t)b * NSEQ) * DMODEL + h * DHD;

    // Load 128x32 Q and K tiles, transposed into SMEM (coalesced global reads).
    for (int e = tid; e < 128 * DHD; e += 256) {
        int r = e >> 5, d = e & 31;
        Qt[d][r] = qb[(size_t)(i0 + r) * DMODEL + d];
        Kt[d][r] = kb[(size_t)(j0 + r) * DMODEL + d];
    }
    __syncthreads();

    int tx = tid & 15, ty = tid >> 4;   // 16x16 thread grid, 8x8 each
    float acc[8][8] = {};
#pragma unroll
    for (int dd = 0; dd < DHD; dd++) {
        float4 qa0 = *reinterpret_cast<const float4*>(&Qt[dd][ty * 8]);
        float4 qa1 = *reinterpret_cast<const float4*>(&Qt[dd][ty * 8 + 4]);
        float4 kb0 = *reinterpret_cast<const float4*>(&Kt[dd][tx * 8]);
        float4 kb1 = *reinterpret_cast<const float4*>(&Kt[dd][tx * 8 + 4]);
        float a8[8] = {qa0.x, qa0.y, qa0.z, qa0.w, qa1.x, qa1.y, qa1.z, qa1.w};
        float b8[8] = {kb0.x, kb0.y, kb0.z, kb0.w, kb1.x, kb1.y, kb1.z, kb1.w};
#pragma unroll
        for (int i = 0; i < 8; i++)
#pragma unroll
            for (int j = 0; j < 8; j++)
                acc[i][j] += a8[i] * b8[j];
    }

    const float scale = 1.0f / sqrtf((float)DHD);
    float* Sp = S + ((size_t)bh * NSEQ + i0) * NSEQ + j0;
#pragma unroll
    for (int i = 0; i < 8; i++) {
        float4 v0 = make_float4(acc[i][0] * scale, acc[i][1] * scale,
                                acc[i][2] * scale, acc[i][3] * scale);
        float4 v1 = make_float4(acc[i][4] * scale, acc[i][5] * scale,
                                acc[i][6] * scale, acc[i][7] * scale);
        float* row = Sp + (size_t)(ty * 8 + i) * NSEQ + tx * 8;
        *reinterpret_cast<float4*>(row) = v0;
        *reinterpret_cast<float4*>(row + 4) = v1;
    }
}

// ---------------------------------------------------------------------------
// Fused per-row: exact top-32 radix select (plain smem atomics — measured
// faster than match_any leader election — plus early exit), deterministic
// compaction, sparse exp + sparse P @ V.
// ---------------------------------------------------------------------------
__device__ __forceinline__ unsigned fkey(float f) {
    unsigned u = __float_as_uint(f);
    return u ^ (((int)u < 0) ? 0xFFFFFFFFu : 0x80000000u);
}

__device__ __forceinline__ float blkReduceMax(float v, float* red) {
#pragma unroll
    for (int o = 16; o; o >>= 1) v = fmaxf(v, __shfl_xor_sync(0xffffffffu, v, o));
    if ((threadIdx.x & 31) == 0) red[threadIdx.x >> 5] = v;
    __syncthreads();
    float m = red[0];
#pragma unroll
    for (int i = 1; i < 8; i++) m = fmaxf(m, red[i]);
    return m;
}

__device__ __forceinline__ float blkReduceSum(float v, float* red) {
#pragma unroll
    for (int o = 16; o; o >>= 1) v += __shfl_xor_sync(0xffffffffu, v, o);
    if ((threadIdx.x & 31) == 0) red[threadIdx.x >> 5] = v;
    __syncthreads();
    float m = red[0];
#pragma unroll
    for (int i = 1; i < 8; i++) m += red[i];
    return m;
}

__global__ void attn_row_kernel() {
    const float* S = g_arena + OFF_SC;
    const float* v = g_arena + OFF_V;
    float* o = g_arena + OFF_O;

    __shared__ unsigned hist[256];
    __shared__ unsigned wsum[8];
    __shared__ int sel_idx[NSEQ];
    __shared__ float sel_p[NSEQ];
    __shared__ float red[8];
    __shared__ float part[256];
    __shared__ unsigned sh_pref, sh_k, sh_done;

    int row = blockIdx.x;
    int n = row & (NSEQ - 1);
    int bh = row >> 11;
    int h = bh & (HH - 1), b = bh >> 3;
    int t = threadIdx.x;
    int lane = t & 31, w = t >> 5;

    const float4* srow4 = reinterpret_cast<const float4*>(
        S + ((size_t)bh * NSEQ + n) * NSEQ);

    // Thread t owns indices 8t..8t+7 (two streaming float4 loads).
    float val8[8];
    unsigned key8[8];
    float4 va = __ldcs(srow4 + 2 * t);
    float4 vb = __ldcs(srow4 + 2 * t + 1);
    val8[0] = va.x; val8[1] = va.y; val8[2] = va.z; val8[3] = va.w;
    val8[4] = vb.x; val8[5] = vb.y; val8[6] = vb.z; val8[7] = vb.w;
    float m = -INFINITY;
#pragma unroll
    for (int r = 0; r < 8; r++) {
        key8[r] = fkey(val8[r]);
        m = fmaxf(m, val8[r]);
    }
    if (t == 0) { sh_pref = 0u; sh_k = KSP; sh_done = 0u; }
    m = blkReduceMax(m, red);   // its sync publishes sh_pref/sh_k/sh_done

    // Radix select: exact 32nd-largest key (ties counted — matches
    // jax.lax.top_k's k-th sorted value under >= threshold semantics).
    // Plain smem atomics (measured faster than match_any leader election).
    // Early exit: if the selected bucket is entirely kept (suf == kneed),
    // thr = prefix with zero low bits is already exact — skip later passes.
#pragma unroll 1
    for (int shift = 24; shift >= 0; shift -= 8) {
        if (sh_done) break;
        hist[t] = 0u;
        unsigned pref = sh_pref;
        unsigned kneed = sh_k;
        __syncthreads();
        unsigned mask = (shift == 24) ? 0u : (0xFFFFFFFFu << (shift + 8));
#pragma unroll
        for (int r = 0; r < 8; r++)
            if ((key8[r] & mask) == pref)
                atomicAdd(&hist[(key8[r] >> shift) & 255u], 1u);
        __syncthreads();
        unsigned own = hist[t];
        // warp-level inclusive suffix scan of the 256 buckets
        unsigned sv = own;
#pragma unroll
        for (int off = 1; off < 32; off <<= 1) {
            unsigned u = __shfl_down_sync(0xffffffffu, sv, off);
            if (lane + off < 32) sv += u;
        }
        if (lane == 0) wsum[w] = sv;
        __syncthreads();
        unsigned add = 0u;
#pragma unroll
        for (int w2 = 0; w2 < 8; w2++)
            if (w2 > w) add += wsum[w2];
        unsigned suf = sv + add;
        if (suf >= kneed && (suf - own) < kneed) {
            sh_pref = pref | ((unsigned)t << shift);
            sh_k = kneed - (suf - own);
            if (suf == kneed) sh_done = 1u;
        }
        __syncthreads();
    }
    unsigned thr = sh_pref;

    // Deterministic compaction (rank by global index order).
    unsigned pass8 = 0u;
    unsigned cnt_t = 0u;
#pragma unroll
    for (int r = 0; r < 8; r++)
        if (key8[r] >= thr) { pass8 |= (1u << r); cnt_t++; }
    unsigned pv = cnt_t;
#pragma unroll
    for (int off = 1; off < 32; off <<= 1) {
        unsigned u = __shfl_up_sync(0xffffffffu, pv, off);
        if (lane >= off) pv += u;
    }
    if (lane == 31) wsum[w] = pv;
    __syncthreads();
    unsigned addp = 0u, cnt_all = 0u;
#pragma unroll
    for (int w2 = 0; w2 < 8; w2++) {
        unsigned ws = wsum[w2];
        if (w2 < w) addp += ws;
        cnt_all += ws;
    }
    int pos = (int)(pv + addp - cnt_t);
    int cnt = (int)cnt_all;
#pragma unroll
    for (int r = 0; r < 8; r++)
        if (pass8 & (1u << r)) {
            sel_idx[pos] = 8 * t + r;
            sel_p[pos] = val8[r];
            pos++;
        }
    __syncthreads();

    // Sparse exp + sum (~32 entries)
    float loc = 0.f;
    for (int e = t; e < cnt; e += 256) {
        float p = __expf(sel_p[e] - m);
        sel_p[e] = p;
        loc += p;
    }
    float tot = blkReduceSum(loc, red);
    float inv = 1.f / tot;

    // Sparse P @ V: warp w handles entries e ≡ w (mod 8); lane gathers
    // V[sel_idx[e]][h*32+lane] — one coalesced 128B row per entry.
    const float* vbp = v + ((size_t)b * NSEQ) * DMODEL + h * DHD + lane;
    float acc = 0.f;
    for (int e = w; e < cnt; e += 8)
        acc += sel_p[e] * vbp[(size_t)sel_idx[e] * DMODEL];
    part[t] = acc;
    __syncthreads();
    if (t < 32) {
        float r = part[t];
#pragma unroll
        for (int ww = 1; ww < 8; ww++) r += part[ww * 32 + t];
        o[((size_t)b * NSEQ + n) * DMODEL + h * DHD + t] = r * inv;
    }
}

// ---------------------------------------------------------------------------
// BatchNorm over (B,N) per channel — deterministic two-stage reduction.
// ---------------------------------------------------------------------------
__global__ void bn_partial_kernel() {
    const float* X = g_arena + OFF_H;
    float* ps = g_arena + OFF_PS;
    float* pq = g_arena + OFF_PQ;
    int blk = blockIdx.x;
    int t = threadIdx.x;
    float s = 0.f, q = 0.f;
    for (int r = 0; r < 128; r++) {
        float val = X[(size_t)(blk * 128 + r) * DMODEL + t];
        s += val;
        q += val * val;
    }
    ps[blk * DMODEL + t] = s;
    pq[blk * DMODEL + t] = q;
}

__global__ void bn_finalize_kernel() {
    const float* ps = g_arena + OFF_PS;
    const float* pq = g_arena + OFF_PQ;
    float* stat = g_arena + OFF_ST;
    int t = threadIdx.x;
    float s = 0.f, q = 0.f;
    for (int b = 0; b < 64; b++) {
        s += ps[b * DMODEL + t];
        q += pq[b * DMODEL + t];
    }
    float mu = s * (1.0f / (float)MROWS);
    float var = q * (1.0f / (float)MROWS) - mu * mu;
    stat[t] = mu;
    stat[DMODEL + t] = rsqrtf(var + 1e-5f);
}

__global__ void bn_apply_kernel(const float* __restrict__ gamma,
                                const float* __restrict__ beta,
                                float* __restrict__ out) {
    const float* X = g_arena + OFF_H;
    const float* stat = g_arena + OFF_ST;
    size_t idx = (size_t)blockIdx.x * 256 + threadIdx.x;
    int c = (int)(idx & (DMODEL - 1));
    out[idx] = (X[idx] - stat[c]) * stat[DMODEL + c] * gamma[c] + beta[c];
}

// ---------------------------------------------------------------------------
// Launch — kernel launches ONLY (graph-capture safe)
// ---------------------------------------------------------------------------
extern "C" void kernel_launch(void* const* d_in, const int* in_sizes, int n_in,
                              void* d_out, int out_size) {
    const float* x    = (const float*)d_in[0];
    const float* U_np = (const float*)d_in[1];
    const float* V_np = (const float*)d_in[2];
    const float* b_np = (const float*)d_in[3];
    const float* U_q  = (const float*)d_in[4];
    const float* V_q  = (const float*)d_in[5];
    const float* U_k  = (const float*)d_in[6];
    const float* V_k  = (const float*)d_in[7];
    const float* U_v  = (const float*)d_in[8];
    const float* V_v  = (const float*)d_in[9];
    const float* U_o  = (const float*)d_in[10];
    const float* V_o  = (const float*)d_in[11];
    const float* b_o  = (const float*)d_in[12];
    const float* U_op = (const float*)d_in[13];
    const float* V_op = (const float*)d_in[14];
    const float* b_op = (const float*)d_in[15];
    const float* gamma = (const float*)d_in[16];
    const float* beta  = (const float*)d_in[17];
    float* out = (float*)d_out;

    dim3 gN1(1, MROWS / 64);        // Nn = 64
    dim3 gN4(4, MROWS / 64);        // Nn = 256
    dim3 gN1z(1, MROWS / 64, 3);    // batched QKV stage-1
    dim3 gN4z(4, MROWS / 64, 3);    // batched QKV stage-2

    // h = (x @ U_np) @ V_np + b_np
    sgemm_kernel<<<gN1, 256>>>(x, 0, U_np, nullptr, OFF_T, RR, DMODEL);
    sgemm_kernel<<<gN4, 256>>>(nullptr, OFF_T, V_np, b_np, OFF_H, DMODEL, RR);
    // q,k,v batched
    sgemm3_kernel<<<gN1z, 256>>>(OFF_H, 0, U_q, U_k, U_v,
                                 OFF_T, (size_t)MROWS * RR, RR, DMODEL);
    sgemm3_kernel<<<gN4z, 256>>>(OFF_T, (size_t)MROWS * RR, V_q, V_k, V_v,
                                 OFF_Q, (size_t)MROWS * DMODEL, DMODEL, RR);

    // scores (128x128 tiles)
    qk_kernel<<<dim3(NSEQ / 128, NSEQ / 128, BSZ * HH), 256>>>();
    // top-k + softmax + sparse PV
    attn_row_kernel<<<BSZ * HH * NSEQ, 256>>>();

    // attention out proj + out_proj
    sgemm_kernel<<<gN1, 256>>>(nullptr, OFF_O, U_o, nullptr, OFF_T, RR, DMODEL);
    sgemm_kernel<<<gN4, 256>>>(nullptr, OFF_T, V_o, b_o, OFF_O2, DMODEL, RR);
    sgemm_kernel<<<gN1, 256>>>(nullptr, OFF_O2, U_op, nullptr, OFF_T, RR, DMODEL);
    sgemm_kernel<<<gN4, 256>>>(nullptr, OFF_T, V_op, b_op, OFF_H, DMODEL, RR);

    // BatchNorm
    bn_partial_kernel<<<64, 256>>>();
    bn_finalize_kernel<<<1, 256>>>();
    bn_apply_kernel<<<(MROWS * DMODEL) / 256, 256>>>(gamma, beta, out);
}

// round 12
// speedup vs baseline: 1.8407x; 1.0829x over previous
#include <cuda_runtime.h>
#include <math.h>
#include <stdint.h>

// Problem constants
#define BSZ 4
#define NSEQ 2048
#define DMODEL 256
#define HH 8
#define DHD 32
#define RR 64
#define KSP 32
#define MROWS (BSZ * NSEQ)   // 8192

// ---------------------------------------------------------------------------
// Scratch arena (float offsets), compile-time indexed.
// ---------------------------------------------------------------------------
#define OFF_T   ((size_t)0)                                   // 3 * 8192*64
#define OFF_H   (OFF_T  + (size_t)3 * MROWS * RR)
#define OFF_Q   (OFF_H  + (size_t)MROWS * DMODEL)
#define OFF_K   (OFF_Q  + (size_t)MROWS * DMODEL)
#define OFF_V   (OFF_K  + (size_t)MROWS * DMODEL)
#define OFF_O   (OFF_V  + (size_t)MROWS * DMODEL)
#define OFF_O2  (OFF_O  + (size_t)MROWS * DMODEL)
#define OFF_SC  (OFF_O2 + (size_t)MROWS * DMODEL)             // 512 MB scores
#define OFF_PS  (OFF_SC + (size_t)BSZ * HH * NSEQ * NSEQ)
#define OFF_PQ  (OFF_PS + (size_t)64 * DMODEL)
#define OFF_ST  (OFF_PQ + (size_t)64 * DMODEL)
#define ARENA_TOTAL (OFF_ST + (size_t)2 * DMODEL)

__device__ float g_arena[ARENA_TOTAL];

// ---------------------------------------------------------------------------
// Shared GEMM body: C[M,N] = A[M,K] @ B[K,N] (+ bias[N])
// ---------------------------------------------------------------------------
__device__ __forceinline__ void gemm_body(const float* __restrict__ A,
                                          const float* __restrict__ Bm,
                                          const float* __restrict__ bias,
                                          float* __restrict__ C,
                                          int Nn, int K) {
    __shared__ float As[16][65];
    __shared__ float Bs[16][65];
    int tid = threadIdx.x;
    int tx = tid & 15, ty = tid >> 4;
    int m0 = blockIdx.y * 64, n0 = blockIdx.x * 64;
    float acc[4][4] = {};

    for (int k0 = 0; k0 < K; k0 += 16) {
#pragma unroll
        for (int r = 0; r < 4; r++) {
            int idx = tid + r * 256;
            int m = idx >> 4;
            int kk = idx & 15;
            As[kk][m] = A[(size_t)(m0 + m) * K + k0 + kk];
        }
#pragma unroll
        for (int r = 0; r < 4; r++) {
            int idx = tid + r * 256;
            int kk = idx >> 6;
            int nn = idx & 63;
            Bs[kk][nn] = Bm[(size_t)(k0 + kk) * Nn + n0 + nn];
        }
        __syncthreads();
#pragma unroll
        for (int kk = 0; kk < 16; kk++) {
            float a4[4], b4[4];
#pragma unroll
            for (int i = 0; i < 4; i++) a4[i] = As[kk][ty * 4 + i];
#pragma unroll
            for (int j = 0; j < 4; j++) b4[j] = Bs[kk][tx * 4 + j];
#pragma unroll
            for (int i = 0; i < 4; i++)
#pragma unroll
                for (int j = 0; j < 4; j++)
                    acc[i][j] += a4[i] * b4[j];
        }
        __syncthreads();
    }
#pragma unroll
    for (int i = 0; i < 4; i++) {
        int m = m0 + ty * 4 + i;
#pragma unroll
        for (int j = 0; j < 4; j++) {
            int n = n0 + tx * 4 + j;
            float v = acc[i][j];
            if (bias) v += bias[n];
            C[(size_t)m * Nn + n] = v;
        }
    }
}

__global__ void sgemm_kernel(const float* __restrict__ Aext, size_t aOff,
                             const float* __restrict__ Bm,
                             const float* __restrict__ bias,
                             size_t cOff, int Nn, int K) {
    const float* A = Aext ? Aext : (g_arena + aOff);
    gemm_body(A, Bm, bias, g_arena + cOff, Nn, K);
}

__global__ void sgemm3_kernel(size_t aOff, size_t aStride,
                              const float* __restrict__ B0,
                              const float* __restrict__ B1,
                              const float* __restrict__ B2,
                              size_t cOff, size_t cStride, int Nn, int K) {
    int z = blockIdx.z;
    const float* Bm = (z == 0) ? B0 : (z == 1) ? B1 : B2;
    gemm_body(g_arena + aOff + (size_t)z * aStride, Bm, nullptr,
              g_arena + cOff + (size_t)z * cStride, Nn, K);
}

// ---------------------------------------------------------------------------
// QK^T scores per (b,h): S[bh][i][j] = (q_i . k_j) / sqrt(32)
// 64x64 tiles (the measured-989 configuration).
// ---------------------------------------------------------------------------
__global__ void qk_kernel() {
    const float* q = g_arena + OFF_Q;
    const float* k = g_arena + OFF_K;
    float* S = g_arena + OFF_SC;
    int bh = blockIdx.z;
    int h = bh & (HH - 1), b = bh >> 3;
    int i0 = blockIdx.y * 64, j0 = blockIdx.x * 64;
    __shared__ float Qs[64][33];
    __shared__ float Ks[64][33];
    int tid = threadIdx.x;
    int d = tid & 31, r0 = tid >> 5;
    const float* qb = q + ((size_t)b * NSEQ) * DMODEL + h * DHD;
    const float* kb = k + ((size_t)b * NSEQ) * DMODEL + h * DHD;
#pragma unroll
    for (int r = r0; r < 64; r += 8) {
        Qs[r][d] = qb[(size_t)(i0 + r) * DMODEL + d];
        Ks[r][d] = kb[(size_t)(j0 + r) * DMODEL + d];
    }
    __syncthreads();
    int tx = tid & 15, ty = tid >> 4;
    float acc[4][4] = {};
#pragma unroll
    for (int dd = 0; dd < 32; dd++) {
        float a4[4], b4[4];
#pragma unroll
        for (int i = 0; i < 4; i++) a4[i] = Qs[ty * 4 + i][dd];
#pragma unroll
        for (int j = 0; j < 4; j++) b4[j] = Ks[tx * 4 + j][dd];
#pragma unroll
        for (int i = 0; i < 4; i++)
#pragma unroll
            for (int j = 0; j < 4; j++)
                acc[i][j] += a4[i] * b4[j];
    }
    const float scale = 1.0f / sqrtf(32.0f);
    float* Sp = S + ((size_t)bh * NSEQ + i0) * NSEQ + j0;
#pragma unroll
    for (int i = 0; i < 4; i++) {
        float4 v4 = make_float4(acc[i][0] * scale, acc[i][1] * scale,
                                acc[i][2] * scale, acc[i][3] * scale);
        *reinterpret_cast<float4*>(Sp + (size_t)(ty * 4 + i) * NSEQ + tx * 4) = v4;
    }
}

// ---------------------------------------------------------------------------
// Fused per-row top-32 + softmax + sparse PV.
// Statistical prefilter (tau from row max/mean) shrinks the exact radix
// select to ~32-400 candidates. Exactness: cnt(>=tau) >= 32 implies
// thr >= tau, so every kept element is a candidate.
// ---------------------------------------------------------------------------
__device__ __forceinline__ unsigned fkey(float f) {
    unsigned u = __float_as_uint(f);
    return u ^ (((int)u < 0) ? 0xFFFFFFFFu : 0x80000000u);
}

// Block reduces with trailing sync (safe for back-to-back use).
__device__ __forceinline__ float blkReduceMax(float v, float* red) {
#pragma unroll
    for (int o = 16; o; o >>= 1) v = fmaxf(v, __shfl_xor_sync(0xffffffffu, v, o));
    if ((threadIdx.x & 31) == 0) red[threadIdx.x >> 5] = v;
    __syncthreads();
    float m = red[0];
#pragma unroll
    for (int i = 1; i < 8; i++) m = fmaxf(m, red[i]);
    __syncthreads();
    return m;
}

__device__ __forceinline__ float blkReduceSum(float v, float* red) {
#pragma unroll
    for (int o = 16; o; o >>= 1) v += __shfl_xor_sync(0xffffffffu, v, o);
    if ((threadIdx.x & 31) == 0) red[threadIdx.x >> 5] = v;
    __syncthreads();
    float m = red[0];
#pragma unroll
    for (int i = 1; i < 8; i++) m += red[i];
    __syncthreads();
    return m;
}

__device__ __forceinline__ unsigned blkReduceSumU(unsigned v, unsigned* wr) {
#pragma unroll
    for (int o = 16; o; o >>= 1) v += __shfl_xor_sync(0xffffffffu, v, o);
    if ((threadIdx.x & 31) == 0) wr[threadIdx.x >> 5] = v;
    __syncthreads();
    unsigned s = 0;
#pragma unroll
    for (int i = 0; i < 8; i++) s += wr[i];
    __syncthreads();
    return s;
}

__global__ void attn_row_kernel() {
    const float* S = g_arena + OFF_SC;
    const float* v = g_arena + OFF_V;
    float* o = g_arena + OFF_O;

    __shared__ unsigned hist[256];
    __shared__ unsigned wsum[8];
    __shared__ int sel_idx[NSEQ];
    __shared__ float sel_p[NSEQ];
    __shared__ float red[8];
    __shared__ float part[256];
    __shared__ unsigned sh_pref, sh_k, sh_done;

    int row = blockIdx.x;
    int n = row & (NSEQ - 1);
    int bh = row >> 11;
    int h = bh & (HH - 1), b = bh >> 3;
    int t = threadIdx.x;
    int lane = t & 31, w = t >> 5;

    const float4* srow4 = reinterpret_cast<const float4*>(
        S + ((size_t)bh * NSEQ + n) * NSEQ);

    // Thread t owns indices 8t..8t+7 (two streaming float4 loads).
    float val8[8];
    float4 va = __ldcs(srow4 + 2 * t);
    float4 vb = __ldcs(srow4 + 2 * t + 1);
    val8[0] = va.x; val8[1] = va.y; val8[2] = va.z; val8[3] = va.w;
    val8[4] = vb.x; val8[5] = vb.y; val8[6] = vb.z; val8[7] = vb.w;
    float mloc = -INFINITY, sloc = 0.f;
#pragma unroll
    for (int r = 0; r < 8; r++) {
        mloc = fmaxf(mloc, val8[r]);
        sloc += val8[r];
    }
    float m = blkReduceMax(mloc, red);
    float mu = blkReduceSum(sloc, red) * (1.0f / (float)NSEQ);

    // Threshold search: start at (m+mu)/2 (~= the top-32 boundary for
    // near-Gaussian rows); halve toward mu until >= 32 candidates.
    // Deterministic fallback to -inf after 4 failed tries.
    float tau = 0.5f * (m + mu);
    unsigned cnt = 0;
#pragma unroll 1
    for (int it = 0; it < 5; it++) {
        unsigned lc = 0;
#pragma unroll
        for (int r = 0; r < 8; r++) lc += (val8[r] >= tau) ? 1u : 0u;
        cnt = blkReduceSumU(lc, wsum);
        if (cnt >= KSP) break;
        tau = (it >= 3) ? -INFINITY : 0.5f * (tau + mu);
    }

    // Compact candidates (val >= tau), deterministic rank by (t, r).
    unsigned pass8 = 0u, cnt_t = 0u;
#pragma unroll
    for (int r = 0; r < 8; r++)
        if (val8[r] >= tau) { pass8 |= (1u << r); cnt_t++; }
    unsigned pv = cnt_t;
#pragma unroll
    for (int off = 1; off < 32; off <<= 1) {
        unsigned u = __shfl_up_sync(0xffffffffu, pv, off);
        if (lane >= off) pv += u;
    }
    if (lane == 31) wsum[w] = pv;
    if (t == 0) { sh_pref = 0u; sh_k = KSP; sh_done = 0u; }
    __syncthreads();
    unsigned addp = 0u, c_all = 0u;
#pragma unroll
    for (int w2 = 0; w2 < 8; w2++) {
        unsigned ws = wsum[w2];
        if (w2 < w) addp += ws;
        c_all += ws;
    }
    int pos = (int)(pv + addp - cnt_t);
    int c = (int)c_all;                 // >= 32 guaranteed
#pragma unroll
    for (int r = 0; r < 8; r++)
        if (pass8 & (1u << r)) {
            sel_idx[pos] = 8 * t + r;
            sel_p[pos] = val8[r];
            pos++;
        }
    __syncthreads();

    // Exact radix select of the 32nd-largest among the c candidates (ties
    // counted — matches jax.lax.top_k's k-th sorted value under >=).
    // Few atomics now (c small). Early exit when the selected bucket is
    // entirely kept (suf == kneed): thr with zero low bits is exact.
#pragma unroll 1
    for (int shift = 24; shift >= 0; shift -= 8) {
        if (sh_done) break;
        hist[t] = 0u;
        unsigned pref = sh_pref;
        unsigned kneed = sh_k;
        __syncthreads();
        unsigned mask = (shift == 24) ? 0u : (0xFFFFFFFFu << (shift + 8));
        for (int e = t; e < c; e += 256) {
            unsigned key = fkey(sel_p[e]);
            if ((key & mask) == pref)
                atomicAdd(&hist[(key >> shift) & 255u], 1u);
        }
        __syncthreads();
        unsigned own = hist[t];
        unsigned sv = own;
#pragma unroll
        for (int off = 1; off < 32; off <<= 1) {
            unsigned u = __shfl_down_sync(0xffffffffu, sv, off);
            if (lane + off < 32) sv += u;
        }
        if (lane == 0) wsum[w] = sv;
        __syncthreads();
        unsigned add = 0u;
#pragma unroll
        for (int w2 = 0; w2 < 8; w2++)
            if (w2 > w) add += wsum[w2];
        unsigned suf = sv + add;
        if (suf >= kneed && (suf - own) < kneed) {
            sh_pref = pref | ((unsigned)t << shift);
            sh_k = kneed - (suf - own);
            if (suf == kneed) sh_done = 1u;
        }
        __syncthreads();
    }
    unsigned thr = sh_pref;

    // Final in-place compaction of kept entries (fkey >= thr) among the
    // candidates. Reads complete before the scan's sync; writes after.
    float kv[8];
    int ki[8];
    unsigned keep8 = 0u, kc = 0u;
#pragma unroll
    for (int i = 0; i < 8; i++) {
        int e = t + 256 * i;
        if (e < c) {
            float x = sel_p[e];
            kv[i] = x;
            ki[i] = sel_idx[e];
            if (fkey(x) >= thr) { keep8 |= (1u << i); kc++; }
        }
    }
    unsigned pv2 = kc;
#pragma unroll
    for (int off = 1; off < 32; off <<= 1) {
        unsigned u = __shfl_up_sync(0xffffffffu, pv2, off);
        if (lane >= off) pv2 += u;
    }
    if (lane == 31) wsum[w] = pv2;
    __syncthreads();
    unsigned addp2 = 0u, c2_all = 0u;
#pragma unroll
    for (int w2 = 0; w2 < 8; w2++) {
        unsigned ws = wsum[w2];
        if (w2 < w) addp2 += ws;
        c2_all += ws;
    }
    int pos2 = (int)(pv2 + addp2 - kc);
    int c2 = (int)c2_all;
#pragma unroll
    for (int i = 0; i < 8; i++)
        if (keep8 & (1u << i)) {
            sel_idx[pos2] = ki[i];
            sel_p[pos2] = kv[i];
            pos2++;
        }
    __syncthreads();

    // Sparse exp + sum over the kept set (~32 entries).
    float loc = 0.f;
    for (int e = t; e < c2; e += 256) {
        float p = __expf(sel_p[e] - m);
        sel_p[e] = p;
        loc += p;
    }
    float tot = blkReduceSum(loc, red);   // its sync publishes sel_p
    float inv = 1.f / tot;

    // Sparse P @ V: warp w handles entries e ≡ w (mod 8); lane gathers
    // V[sel_idx[e]][h*32+lane] — one coalesced 128B row per entry.
    const float* vbp = v + ((size_t)b * NSEQ) * DMODEL + h * DHD + lane;
    float acc = 0.f;
    for (int e = w; e < c2; e += 8)
        acc += sel_p[e] * vbp[(size_t)sel_idx[e] * DMODEL];
    part[t] = acc;
    __syncthreads();
    if (t < 32) {
        float r = part[t];
#pragma unroll
        for (int ww = 1; ww < 8; ww++) r += part[ww * 32 + t];
        o[((size_t)b * NSEQ + n) * DMODEL + h * DHD + t] = r * inv;
    }
}

// ---------------------------------------------------------------------------
// BatchNorm over (B,N) per channel — deterministic two-stage reduction.
// ---------------------------------------------------------------------------
__global__ void bn_partial_kernel() {
    const float* X = g_arena + OFF_H;
    float* ps = g_arena + OFF_PS;
    float* pq = g_arena + OFF_PQ;
    int blk = blockIdx.x;
    int t = threadIdx.x;
    float s = 0.f, q = 0.f;
    for (int r = 0; r < 128; r++) {
        float val = X[(size_t)(blk * 128 + r) * DMODEL + t];
        s += val;
        q += val * val;
    }
    ps[blk * DMODEL + t] = s;
    pq[blk * DMODEL + t] = q;
}

__global__ void bn_finalize_kernel() {
    const float* ps = g_arena + OFF_PS;
    const float* pq = g_arena + OFF_PQ;
    float* stat = g_arena + OFF_ST;
    int t = threadIdx.x;
    float s = 0.f, q = 0.f;
    for (int b = 0; b < 64; b++) {
        s += ps[b * DMODEL + t];
        q += pq[b * DMODEL + t];
    }
    float mu = s * (1.0f / (float)MROWS);
    float var = q * (1.0f / (float)MROWS) - mu * mu;
    stat[t] = mu;
    stat[DMODEL + t] = rsqrtf(var + 1e-5f);
}

__global__ void bn_apply_kernel(const float* __restrict__ gamma,
                                const float* __restrict__ beta,
                                float* __restrict__ out) {
    const float* X = g_arena + OFF_H;
    const float* stat = g_arena + OFF_ST;
    size_t idx = (size_t)blockIdx.x * 256 + threadIdx.x;
    int c = (int)(idx & (DMODEL - 1));
    out[idx] = (X[idx] - stat[c]) * stat[DMODEL + c] * gamma[c] + beta[c];
}

// ---------------------------------------------------------------------------
// Launch — kernel launches ONLY (graph-capture safe)
// ---------------------------------------------------------------------------
extern "C" void kernel_launch(void* const* d_in, const int* in_sizes, int n_in,
                              void* d_out, int out_size) {
    const float* x    = (const float*)d_in[0];
    const float* U_np = (const float*)d_in[1];
    const float* V_np = (const float*)d_in[2];
    const float* b_np = (const float*)d_in[3];
    const float* U_q  = (const float*)d_in[4];
    const float* V_q  = (const float*)d_in[5];
    const float* U_k  = (const float*)d_in[6];
    const float* V_k  = (const float*)d_in[7];
    const float* U_v  = (const float*)d_in[8];
    const float* V_v  = (const float*)d_in[9];
    const float* U_o  = (const float*)d_in[10];
    const float* V_o  = (const float*)d_in[11];
    const float* b_o  = (const float*)d_in[12];
    const float* U_op = (const float*)d_in[13];
    const float* V_op = (const float*)d_in[14];
    const float* b_op = (const float*)d_in[15];
    const float* gamma = (const float*)d_in[16];
    const float* beta  = (const float*)d_in[17];
    float* out = (float*)d_out;

    dim3 gN1(1, MROWS / 64);        // Nn = 64
    dim3 gN4(4, MROWS / 64);        // Nn = 256
    dim3 gN1z(1, MROWS / 64, 3);    // batched QKV stage-1
    dim3 gN4z(4, MROWS / 64, 3);    // batched QKV stage-2

    // h = (x @ U_np) @ V_np + b_np
    sgemm_kernel<<<gN1, 256>>>(x, 0, U_np, nullptr, OFF_T, RR, DMODEL);
    sgemm_kernel<<<gN4, 256>>>(nullptr, OFF_T, V_np, b_np, OFF_H, DMODEL, RR);
    // q,k,v batched
    sgemm3_kernel<<<gN1z, 256>>>(OFF_H, 0, U_q, U_k, U_v,
                                 OFF_T, (size_t)MROWS * RR, RR, DMODEL);
    sgemm3_kernel<<<gN4z, 256>>>(OFF_T, (size_t)MROWS * RR, V_q, V_k, V_v,
                                 OFF_Q, (size_t)MROWS * DMODEL, DMODEL, RR);

    // scores (64x64 tiles — the measured-989 config)
    qk_kernel<<<dim3(NSEQ / 64, NSEQ / 64, BSZ * HH), 256>>>();
    // top-k + softmax + sparse PV
    attn_row_kernel<<<BSZ * HH * NSEQ, 256>>>();

    // attention out proj + out_proj
    sgemm_kernel<<<gN1, 256>>>(nullptr, OFF_O, U_o, nullptr, OFF_T, RR, DMODEL);
    sgemm_kernel<<<gN4, 256>>>(nullptr, OFF_T, V_o, b_o, OFF_O2, DMODEL, RR);
    sgemm_kernel<<<gN1, 256>>>(nullptr, OFF_O2, U_op, nullptr, OFF_T, RR, DMODEL);
    sgemm_kernel<<<gN4, 256>>>(nullptr, OFF_T, V_op, b_op, OFF_H, DMODEL, RR);

    // BatchNorm
    bn_partial_kernel<<<64, 256>>>();
    bn_finalize_kernel<<<1, 256>>>();
    bn_apply_kernel<<<(MROWS * DMODEL) / 256, 256>>>(gamma, beta, out);
}